// round 1
// baseline (speedup 1.0000x reference)
#include <cuda_runtime.h>

// DTW loss: B=16, C=8, T=512 -> 128 independent 512x512 DTW DPs.
// Wavefront-skewed execution: one block (128 threads / 4 warps) per (b,c) pair.
// Lane l owns 4 contiguous columns; at step s it computes row i = s - l + 1.
// "left"/"diag" propagate from lane l-1 via shfl_up (intra-warp) and a
// double-buffered shared slot + one __syncthreads per step (warp boundary).
// "up" values are the lane's own previous-row v's (registers).

#define TT    512
#define LANES 128
#define NWARP 4
#define BIGF  1e30f

__device__ float g_partials[128];

__global__ __launch_bounds__(128, 1)
void dtw_wavefront_kernel(const float* __restrict__ inputs,
                          const float* __restrict__ targets) {
    const int p   = blockIdx.x;          // pair index 0..127
    const float* x = inputs  + p * TT;
    const float* y = targets + p * TT;
    const int tid  = threadIdx.x;        // global lane 0..127
    const int lane = tid & 31;
    const int warp = tid >> 5;

    __shared__ float xs[TT];
    __shared__ float hand[NWARP][2];     // [warp][parity]: carry of that warp's lane 31

    for (int k = tid; k < TT; k += 128) xs[k] = x[k];

    // This lane's 4 column values of y (DP columns j = 4*tid+1 .. 4*tid+4)
    const float y0 = y[tid * 4 + 0];
    const float y1 = y[tid * 4 + 1];
    const float y2 = y[tid * 4 + 2];
    const float y3 = y[tid * 4 + 3];

    // Row 0 of the DP table is BIG for all owned columns.
    float up0 = BIGF, up1 = BIGF, up2 = BIGF, up3 = BIGF;
    float carry     = BIGF;              // v of last owned column, previous step
    float left_prev = BIGF;              // left received in previous step (becomes diag)

    __syncthreads();

    const int S = TT + LANES - 1;        // 639 wavefront steps
    for (int s = 0; s < S; ++s) {
        const int buf = s & 1;
        // Publish previous-step carry across the warp boundary.
        if (lane == 31) hand[warp][buf] = carry;
        __syncthreads();

        // left(i, j0) = dtw[i][j0-1], produced by lane-1 in the previous step.
        float left = __shfl_up_sync(0xffffffffu, carry, 1);
        if (lane == 0)
            left = (warp == 0) ? BIGF : hand[warp - 1][buf];

        const int i = s - tid + 1;       // DP row 1..TT
        if (i >= 1 && i <= TT) {
            // diag of first owned column = dtw[i-1][j0-1]:
            //   row 1: dtw[0][j0-1] = BIG, except lane 0 where dtw[0][0] = 0.
            //   row >1: the left we received last step.
            float diag0 = (i == 1) ? ((tid == 0) ? 0.0f : BIGF) : left_prev;
            const float xi = xs[i - 1];

            // Costs and min(up,diag) are off the critical chain.
            const float c0 = fabsf(xi - y0);
            const float c1 = fabsf(xi - y1);
            const float c2 = fabsf(xi - y2);
            const float c3 = fabsf(xi - y3);
            const float m0 = fminf(up0, diag0);
            const float m1 = fminf(up1, up0);   // diag of col k (k>0) = up[k-1]
            const float m2 = fminf(up2, up1);
            const float m3 = fminf(up3, up2);

            // Critical chain: 4 x (FMNMX + FADD)
            const float v0 = c0 + fminf(left, m0);
            const float v1 = c1 + fminf(v0,   m1);
            const float v2 = c2 + fminf(v1,   m2);
            const float v3 = c3 + fminf(v2,   m3);

            up0 = v0; up1 = v1; up2 = v2; up3 = v3;
            carry     = v3;
            left_prev = left;
        }
    }

    // Lane 127 finished row TT at step S-1; carry = dtw[T][T].
    if (tid == LANES - 1)
        g_partials[p] = carry * (1.0f / (float)TT);
}

// Deterministic final reduction: out = sum(partials) / C   (C = 8)
__global__ void dtw_reduce_kernel(float* __restrict__ out) {
    const int t = threadIdx.x;           // 128 threads
    float v = g_partials[t];
    #pragma unroll
    for (int o = 16; o > 0; o >>= 1)
        v += __shfl_down_sync(0xffffffffu, v, o);
    __shared__ float ws[4];
    if ((t & 31) == 0) ws[t >> 5] = v;
    __syncthreads();
    if (t == 0)
        out[0] = (ws[0] + ws[1] + ws[2] + ws[3]) * (1.0f / 8.0f);
}

extern "C" void kernel_launch(void* const* d_in, const int* in_sizes, int n_in,
                              void* d_out, int out_size) {
    const float* inputs  = (const float*)d_in[0];
    const float* targets = (const float*)d_in[1];
    float* out = (float*)d_out;
    (void)in_sizes; (void)n_in; (void)out_size;

    dtw_wavefront_kernel<<<128, 128>>>(inputs, targets);
    dtw_reduce_kernel<<<1, 128>>>(out);
}